// round 3
// baseline (speedup 1.0000x reference)
#include <cuda_runtime.h>
#include <cstdint>

// Problem constants
#define BATCH 4096
#define TT    120
#define II    64
#define HH    128
#define G3    384   // 3*H

typedef unsigned long long u64;

// 755MB fp32 scratch for precomputed input gates, layout [T][B][3H]
__device__ float g_xg[(size_t)TT * BATCH * G3];

// ---------------- packed f32x2 helpers (sm_103a FFMA2) ----------------
__device__ __forceinline__ u64 ffma2(u64 a, u64 b, u64 c) {
    u64 d;
    asm("fma.rn.f32x2 %0, %1, %2, %3;" : "=l"(d) : "l"(a), "l"(b), "l"(c));
    return d;
}
__device__ __forceinline__ u64 pack2(float x, float y) {
    u64 d;
    asm("mov.b64 %0, {%1, %2};" : "=l"(d) : "f"(x), "f"(y));
    return d;
}
__device__ __forceinline__ void unpack2(u64 a, float& x, float& y) {
    asm("mov.b64 {%0, %1}, %2;" : "=f"(x), "=f"(y) : "l"(a));
}

__device__ __forceinline__ float sigf(float v) {
    return __fdividef(1.0f, 1.0f + __expf(-v));
}
__device__ __forceinline__ float tanhf_fast(float v) {
    return __fdividef(2.0f, 1.0f + __expf(-2.0f * v)) - 1.0f;
}

// =====================================================================
// Kernel 1: x_gates[t][b][g] = x[b][t][:] @ W_ih[g][:] + b_ih[g]
// SMEM: Wt[64][385] transposed, bias[384], xT[64][36] (pad 36 => 16B-
// aligned LDS.128 on 8-row groups). 109.3KB -> 2 CTAs/SM.
// =====================================================================
#define XP_WPAD 385
#define XP_HPAD 36
#define XP_SMEM_FLOATS (II * XP_WPAD + G3 + II * XP_HPAD)
#define NTILES (TT * (BATCH / 32))   // 15360

__global__ void __launch_bounds__(512)
xproj_kernel(const float* __restrict__ x,
             const float* __restrict__ Wih,
             const float* __restrict__ bih)
{
    extern __shared__ float sm[];
    float* Wt   = sm;                    // [64][385]
    float* bias = Wt + II * XP_WPAD;     // [384]
    float* xT   = bias + G3;             // [64][36]

    const int tid = threadIdx.x;

    for (int i = tid; i < G3 * II; i += 512) {
        int n = i >> 6;
        int k = i & 63;
        Wt[k * XP_WPAD + n] = Wih[i];
    }
    for (int i = tid; i < G3; i += 512) bias[i] = bih[i];
    __syncthreads();

    const int j     = tid & 127;
    const int mg    = tid >> 7;
    const int mbase = mg * 8;
    const float br = bias[j], bz = bias[128 + j], bn = bias[256 + j];

    for (int tile = blockIdx.x; tile < NTILES; tile += gridDim.x) {
        const int t  = tile % TT;
        const int b0 = (tile / TT) << 5;

        // load x tile transposed: xT[k][m] = x[b0+m][t][k]
        for (int i = tid; i < 32 * II; i += 512) {
            int m = i >> 6;
            int k = i & 63;
            xT[k * XP_HPAD + m] = x[((size_t)(b0 + m) * TT + t) * II + k];
        }
        __syncthreads();

        u64 ar[4], az[4], an[4];
#pragma unroll
        for (int p = 0; p < 4; ++p) { ar[p] = 0ull; az[p] = 0ull; an[p] = 0ull; }

#pragma unroll 4
        for (int k = 0; k < II; ++k) {
            const float* wrow = Wt + k * XP_WPAD;
            float wr = wrow[j], wz = wrow[128 + j], wn = wrow[256 + j];
            u64 wr2 = pack2(wr, wr), wz2 = pack2(wz, wz), wn2 = pack2(wn, wn);
            const ulonglong2* hp =
                reinterpret_cast<const ulonglong2*>(xT + k * XP_HPAD + mbase);
            ulonglong2 ha = hp[0];
            ulonglong2 hb = hp[1];
            u64 h2[4] = {ha.x, ha.y, hb.x, hb.y};
#pragma unroll
            for (int p = 0; p < 4; ++p) {
                ar[p] = ffma2(h2[p], wr2, ar[p]);
                az[p] = ffma2(h2[p], wz2, az[p]);
                an[p] = ffma2(h2[p], wn2, an[p]);
            }
        }

#pragma unroll
        for (int p = 0; p < 4; ++p) {
            float r0, r1, z0, z1, n0, n1;
            unpack2(ar[p], r0, r1);
            unpack2(az[p], z0, z1);
            unpack2(an[p], n0, n1);
#pragma unroll
            for (int e = 0; e < 2; ++e) {
                int mm = 2 * p + e;
                float vr = e ? r1 : r0;
                float vz = e ? z1 : z0;
                float vn = e ? n1 : n0;
                float* g = &g_xg[((size_t)t * BATCH + b0 + mbase + mm) * G3];
                g[j]       = vr + br;
                g[128 + j] = vz + bz;
                g[256 + j] = vn + bn;
            }
        }
        __syncthreads();
    }
}

// =====================================================================
// Kernel 2: fused GRU recurrence. 128 CTAs x 32 batch rows each.
// SMEM: Wt[128][385], bias[384], hT[128][36] (pad 36 => LDS.128).
// Thread (j = tid&127, mg = tid>>7) owns gate columns {j, j+128, j+256}
// for rows m = mg*8 .. mg*8+7; h_old for those (j,m) kept in registers.
// =====================================================================
#define R_WPAD 385
#define R_HPAD 36
#define R_SMEM_FLOATS (HH * R_WPAD + G3 + HH * R_HPAD)

__global__ void __launch_bounds__(512)
gru_rec_kernel(const float* __restrict__ Whh,
               const float* __restrict__ bhh,
               float* __restrict__ out,
               int write_hT)
{
    extern __shared__ float sm[];
    float* Wt   = sm;                    // [128][385]
    float* bias = Wt + HH * R_WPAD;      // [384]
    float* hT   = bias + G3;             // [128][36], hT[k][m]

    const int tid = threadIdx.x;

    for (int i = tid; i < G3 * HH; i += 512) {
        int n = i >> 7;
        int k = i & 127;
        Wt[k * R_WPAD + n] = Whh[i];
    }
    for (int i = tid; i < G3; i += 512) bias[i] = bhh[i];
    for (int i = tid; i < HH * R_HPAD; i += 512) hT[i] = 0.0f;
    __syncthreads();

    const int j     = tid & 127;
    const int mg    = tid >> 7;
    const int mbase = mg * 8;
    const int b0    = blockIdx.x << 5;
    const float br = bias[j], bz = bias[128 + j], bn = bias[256 + j];

    float hold[8];
#pragma unroll
    for (int mm = 0; mm < 8; ++mm) hold[mm] = 0.0f;

    for (int t = 0; t < TT; ++t) {
        // Prefetch input gates early (independent of h) to hide DRAM latency
        float xr[8], xz[8], xn[8];
#pragma unroll
        for (int mm = 0; mm < 8; ++mm) {
            const float* g = &g_xg[((size_t)t * BATCH + b0 + mbase + mm) * G3];
            xr[mm] = g[j];
            xz[mm] = g[128 + j];
            xn[mm] = g[256 + j];
        }

        u64 ar[4], az[4], an[4];
#pragma unroll
        for (int p = 0; p < 4; ++p) { ar[p] = 0ull; az[p] = 0ull; an[p] = 0ull; }

#pragma unroll 4
        for (int k = 0; k < HH; ++k) {
            const float* wrow = Wt + k * R_WPAD;
            float wr = wrow[j], wz = wrow[128 + j], wn = wrow[256 + j];
            u64 wr2 = pack2(wr, wr), wz2 = pack2(wz, wz), wn2 = pack2(wn, wn);
            const ulonglong2* hp =
                reinterpret_cast<const ulonglong2*>(hT + k * R_HPAD + mbase);
            ulonglong2 ha = hp[0];   // broadcast (same addr across warp)
            ulonglong2 hb = hp[1];
            u64 h2[4] = {ha.x, ha.y, hb.x, hb.y};
#pragma unroll
            for (int p = 0; p < 4; ++p) {
                ar[p] = ffma2(h2[p], wr2, ar[p]);
                az[p] = ffma2(h2[p], wz2, az[p]);
                an[p] = ffma2(h2[p], wn2, an[p]);
            }
        }

        float hnew[8];
#pragma unroll
        for (int p = 0; p < 4; ++p) {
            float r0, r1, z0, z1, n0, n1;
            unpack2(ar[p], r0, r1);
            unpack2(az[p], z0, z1);
            unpack2(an[p], n0, n1);
#pragma unroll
            for (int e = 0; e < 2; ++e) {
                int mm = 2 * p + e;
                float hrv = e ? r1 : r0;
                float hzv = e ? z1 : z0;
                float hnv = e ? n1 : n0;
                float r  = sigf(xr[mm] + hrv + br);
                float z  = sigf(xz[mm] + hzv + bz);
                float nn = tanhf_fast(xn[mm] + r * (hnv + bn));
                float hv = nn + z * (hold[mm] - nn);
                hnew[mm] = hv;
                hold[mm] = hv;
                out[((size_t)(b0 + mbase + mm) * TT + t) * HH + j] = hv;
            }
        }
        __syncthreads();            // all reads of old h done
        {   // vectorized writeback: hT[j][mbase..mbase+7]
            float4* dst = reinterpret_cast<float4*>(hT + j * R_HPAD + mbase);
            dst[0] = make_float4(hnew[0], hnew[1], hnew[2], hnew[3]);
            dst[1] = make_float4(hnew[4], hnew[5], hnew[6], hnew[7]);
        }
        __syncthreads();            // new h visible before next step
    }

    if (write_hT) {
        float* outF = out + (size_t)BATCH * TT * HH;
#pragma unroll
        for (int mm = 0; mm < 8; ++mm)
            outF[(size_t)(b0 + mbase + mm) * HH + j] = hold[mm];
    }
}

// =====================================================================
extern "C" void kernel_launch(void* const* d_in, const int* in_sizes, int n_in,
                              void* d_out, int out_size)
{
    const float* x   = (const float*)d_in[0];
    const float* Wih = (const float*)d_in[1];
    const float* Whh = (const float*)d_in[2];
    const float* bih = (const float*)d_in[3];
    const float* bhh = (const float*)d_in[4];
    float* out = (float*)d_out;
    (void)in_sizes; (void)n_in;

    const int xp_smem = XP_SMEM_FLOATS * sizeof(float);   // ~109.3 KB -> 2 CTA/SM
    const int r_smem  = R_SMEM_FLOATS  * sizeof(float);   // ~217.1 KB

    cudaFuncSetAttribute(xproj_kernel,
                         cudaFuncAttributeMaxDynamicSharedMemorySize, xp_smem);
    cudaFuncSetAttribute(gru_rec_kernel,
                         cudaFuncAttributeMaxDynamicSharedMemorySize, r_smem);

    int write_hT = (out_size >= BATCH * TT * HH + BATCH * HH) ? 1 : 0;

    xproj_kernel<<<296, 512, xp_smem>>>(x, Wih, bih);
    gru_rec_kernel<<<BATCH / 32, 512, r_smem>>>(Whh, bhh, out, write_hT);
}

// round 4
// speedup vs baseline: 1.0563x; 1.0563x over previous
#include <cuda_runtime.h>
#include <cstdint>

// Problem constants
#define BATCH 4096
#define TT    120
#define II    64
#define HH    128
#define G3    384   // 3*H

typedef unsigned long long u64;

// 755MB fp32 scratch for precomputed input gates, layout [T][B][3H]
__device__ float g_xg[(size_t)TT * BATCH * G3];

// ---------------- packed f32x2 helpers (sm_103a FFMA2) ----------------
__device__ __forceinline__ u64 ffma2(u64 a, u64 b, u64 c) {
    u64 d;
    asm("fma.rn.f32x2 %0, %1, %2, %3;" : "=l"(d) : "l"(a), "l"(b), "l"(c));
    return d;
}
__device__ __forceinline__ u64 pack2(float x, float y) {
    u64 d;
    asm("mov.b64 %0, {%1, %2};" : "=l"(d) : "f"(x), "f"(y));
    return d;
}
__device__ __forceinline__ void unpack2(u64 a, float& x, float& y) {
    asm("mov.b64 {%0, %1}, %2;" : "=f"(x), "=f"(y) : "l"(a));
}

__device__ __forceinline__ float sigf(float v) {
    return __fdividef(1.0f, 1.0f + __expf(-v));
}
__device__ __forceinline__ float tanhf_fast(float v) {
    return __fdividef(2.0f, 1.0f + __expf(-2.0f * v)) - 1.0f;
}

// =====================================================================
// Kernel 1: x_gates[t][b][g] = x[b][t][:] @ W_ih[g][:] + b_ih[g]
// SMEM: Wt[64][385] transposed, bias[384], xT[64][36] (pad 36 => 16B-
// aligned LDS.128 on 8-row groups). 109.3KB -> 2 CTAs/SM.
// =====================================================================
#define XP_WPAD 385
#define XP_HPAD 36
#define XP_SMEM_FLOATS (II * XP_WPAD + G3 + II * XP_HPAD)
#define NTILES (TT * (BATCH / 32))   // 15360

__global__ void __launch_bounds__(512)
xproj_kernel(const float* __restrict__ x,
             const float* __restrict__ Wih,
             const float* __restrict__ bih)
{
    extern __shared__ float sm[];
    float* Wt   = sm;                    // [64][385]
    float* bias = Wt + II * XP_WPAD;     // [384]
    float* xT   = bias + G3;             // [64][36]

    const int tid = threadIdx.x;

    for (int i = tid; i < G3 * II; i += 512) {
        int n = i >> 6;
        int k = i & 63;
        Wt[k * XP_WPAD + n] = Wih[i];
    }
    for (int i = tid; i < G3; i += 512) bias[i] = bih[i];
    __syncthreads();

    const int j     = tid & 127;
    const int mg    = tid >> 7;
    const int mbase = mg * 8;
    const float br = bias[j], bz = bias[128 + j], bn = bias[256 + j];

    for (int tile = blockIdx.x; tile < NTILES; tile += gridDim.x) {
        const int t  = tile % TT;
        const int b0 = (tile / TT) << 5;

        // load x tile transposed: xT[k][m] = x[b0+m][t][k]
        for (int i = tid; i < 32 * II; i += 512) {
            int m = i >> 6;
            int k = i & 63;
            xT[k * XP_HPAD + m] = x[((size_t)(b0 + m) * TT + t) * II + k];
        }
        __syncthreads();

        u64 ar[4], az[4], an[4];
#pragma unroll
        for (int p = 0; p < 4; ++p) { ar[p] = 0ull; az[p] = 0ull; an[p] = 0ull; }

#pragma unroll 4
        for (int k = 0; k < II; ++k) {
            const float* wrow = Wt + k * XP_WPAD;
            float wr = wrow[j], wz = wrow[128 + j], wn = wrow[256 + j];
            u64 wr2 = pack2(wr, wr), wz2 = pack2(wz, wz), wn2 = pack2(wn, wn);
            const ulonglong2* hp =
                reinterpret_cast<const ulonglong2*>(xT + k * XP_HPAD + mbase);
            ulonglong2 ha = hp[0];
            ulonglong2 hb = hp[1];
            u64 h2[4] = {ha.x, ha.y, hb.x, hb.y};
#pragma unroll
            for (int p = 0; p < 4; ++p) {
                ar[p] = ffma2(h2[p], wr2, ar[p]);
                az[p] = ffma2(h2[p], wz2, az[p]);
                an[p] = ffma2(h2[p], wn2, an[p]);
            }
        }

#pragma unroll
        for (int p = 0; p < 4; ++p) {
            float r0, r1, z0, z1, n0, n1;
            unpack2(ar[p], r0, r1);
            unpack2(az[p], z0, z1);
            unpack2(an[p], n0, n1);
#pragma unroll
            for (int e = 0; e < 2; ++e) {
                int mm = 2 * p + e;
                float vr = e ? r1 : r0;
                float vz = e ? z1 : z0;
                float vn = e ? n1 : n0;
                float* g = &g_xg[((size_t)t * BATCH + b0 + mbase + mm) * G3];
                g[j]       = vr + br;
                g[128 + j] = vz + bz;
                g[256 + j] = vn + bn;
            }
        }
        __syncthreads();
    }
}

// =====================================================================
// Kernel 2: fused GRU recurrence. 128 CTAs x 32 batch rows each.
// SMEM: Wt[128][385], bias[384], hT[128][36] (pad 36 => LDS.128).
// Thread (j = tid&127, mg = tid>>7) owns gate columns {j, j+128, j+256}
// for rows m = mg*8 .. mg*8+7; h_old for those (j,m) kept in registers.
// =====================================================================
#define R_WPAD 385
#define R_HPAD 36
#define R_SMEM_FLOATS (HH * R_WPAD + G3 + HH * R_HPAD)

__global__ void __launch_bounds__(512)
gru_rec_kernel(const float* __restrict__ Whh,
               const float* __restrict__ bhh,
               float* __restrict__ out,
               int write_hT)
{
    extern __shared__ float sm[];
    float* Wt   = sm;                    // [128][385]
    float* bias = Wt + HH * R_WPAD;      // [384]
    float* hT   = bias + G3;             // [128][36], hT[k][m]

    const int tid = threadIdx.x;

    for (int i = tid; i < G3 * HH; i += 512) {
        int n = i >> 7;
        int k = i & 127;
        Wt[k * R_WPAD + n] = Whh[i];
    }
    for (int i = tid; i < G3; i += 512) bias[i] = bhh[i];
    for (int i = tid; i < HH * R_HPAD; i += 512) hT[i] = 0.0f;
    __syncthreads();

    const int j     = tid & 127;
    const int mg    = tid >> 7;
    const int mbase = mg * 8;
    const int b0    = blockIdx.x << 5;
    const float br = bias[j], bz = bias[128 + j], bn = bias[256 + j];

    float hold[8];
#pragma unroll
    for (int mm = 0; mm < 8; ++mm) hold[mm] = 0.0f;

    for (int t = 0; t < TT; ++t) {
        // Prefetch input gates early (independent of h) to hide DRAM latency
        float xr[8], xz[8], xn[8];
#pragma unroll
        for (int mm = 0; mm < 8; ++mm) {
            const float* g = &g_xg[((size_t)t * BATCH + b0 + mbase + mm) * G3];
            xr[mm] = g[j];
            xz[mm] = g[128 + j];
            xn[mm] = g[256 + j];
        }

        u64 ar[4], az[4], an[4];
#pragma unroll
        for (int p = 0; p < 4; ++p) { ar[p] = 0ull; az[p] = 0ull; an[p] = 0ull; }

#pragma unroll 4
        for (int k = 0; k < HH; ++k) {
            const float* wrow = Wt + k * R_WPAD;
            float wr = wrow[j], wz = wrow[128 + j], wn = wrow[256 + j];
            u64 wr2 = pack2(wr, wr), wz2 = pack2(wz, wz), wn2 = pack2(wn, wn);
            const ulonglong2* hp =
                reinterpret_cast<const ulonglong2*>(hT + k * R_HPAD + mbase);
            ulonglong2 ha = hp[0];   // broadcast (same addr across warp)
            ulonglong2 hb = hp[1];
            u64 h2[4] = {ha.x, ha.y, hb.x, hb.y};
#pragma unroll
            for (int p = 0; p < 4; ++p) {
                ar[p] = ffma2(h2[p], wr2, ar[p]);
                az[p] = ffma2(h2[p], wz2, az[p]);
                an[p] = ffma2(h2[p], wn2, an[p]);
            }
        }

        float hnew[8];
#pragma unroll
        for (int p = 0; p < 4; ++p) {
            float r0, r1, z0, z1, n0, n1;
            unpack2(ar[p], r0, r1);
            unpack2(az[p], z0, z1);
            unpack2(an[p], n0, n1);
#pragma unroll
            for (int e = 0; e < 2; ++e) {
                int mm = 2 * p + e;
                float hrv = e ? r1 : r0;
                float hzv = e ? z1 : z0;
                float hnv = e ? n1 : n0;
                float r  = sigf(xr[mm] + hrv + br);
                float z  = sigf(xz[mm] + hzv + bz);
                float nn = tanhf_fast(xn[mm] + r * (hnv + bn));
                float hv = nn + z * (hold[mm] - nn);
                hnew[mm] = hv;
                hold[mm] = hv;
                out[((size_t)(b0 + mbase + mm) * TT + t) * HH + j] = hv;
            }
        }
        __syncthreads();            // all reads of old h done
        {   // vectorized writeback: hT[j][mbase..mbase+7]
            float4* dst = reinterpret_cast<float4*>(hT + j * R_HPAD + mbase);
            dst[0] = make_float4(hnew[0], hnew[1], hnew[2], hnew[3]);
            dst[1] = make_float4(hnew[4], hnew[5], hnew[6], hnew[7]);
        }
        __syncthreads();            // new h visible before next step
    }

    if (write_hT) {
        float* outF = out + (size_t)BATCH * TT * HH;
#pragma unroll
        for (int mm = 0; mm < 8; ++mm)
            outF[(size_t)(b0 + mbase + mm) * HH + j] = hold[mm];
    }
}

// =====================================================================
extern "C" void kernel_launch(void* const* d_in, const int* in_sizes, int n_in,
                              void* d_out, int out_size)
{
    const float* x   = (const float*)d_in[0];
    const float* Wih = (const float*)d_in[1];
    const float* Whh = (const float*)d_in[2];
    const float* bih = (const float*)d_in[3];
    const float* bhh = (const float*)d_in[4];
    float* out = (float*)d_out;
    (void)in_sizes; (void)n_in;

    const int xp_smem = XP_SMEM_FLOATS * sizeof(float);   // ~109.3 KB -> 2 CTA/SM
    const int r_smem  = R_SMEM_FLOATS  * sizeof(float);   // ~217.1 KB

    cudaFuncSetAttribute(xproj_kernel,
                         cudaFuncAttributeMaxDynamicSharedMemorySize, xp_smem);
    cudaFuncSetAttribute(gru_rec_kernel,
                         cudaFuncAttributeMaxDynamicSharedMemorySize, r_smem);

    int write_hT = (out_size >= BATCH * TT * HH + BATCH * HH) ? 1 : 0;

    xproj_kernel<<<296, 512, xp_smem>>>(x, Wih, bih);
    gru_rec_kernel<<<BATCH / 32, 512, r_smem>>>(Whh, bhh, out, write_hT);
}

// round 5
// speedup vs baseline: 1.0952x; 1.0368x over previous
#include <cuda_runtime.h>
#include <cstdint>

// Problem constants
#define BATCH 4096
#define TT    120
#define II    64
#define HH    128
#define G3    384   // 3*H

typedef unsigned long long u64;

// 755MB fp32 scratch for precomputed input gates, layout [T][B][3H]
__device__ float g_xg[(size_t)TT * BATCH * G3];

// ---------------- packed f32x2 helpers (sm_103a FFMA2) ----------------
__device__ __forceinline__ u64 ffma2(u64 a, u64 b, u64 c) {
    u64 d;
    asm("fma.rn.f32x2 %0, %1, %2, %3;" : "=l"(d) : "l"(a), "l"(b), "l"(c));
    return d;
}
__device__ __forceinline__ u64 pack2(float x, float y) {
    u64 d;
    asm("mov.b64 %0, {%1, %2};" : "=l"(d) : "f"(x), "f"(y));
    return d;
}
__device__ __forceinline__ void unpack2(u64 a, float& x, float& y) {
    asm("mov.b64 {%0, %1}, %2;" : "=f"(x), "=f"(y) : "l"(a));
}

__device__ __forceinline__ float sigf(float v) {
    return __fdividef(1.0f, 1.0f + __expf(-v));
}
__device__ __forceinline__ float tanhf_fast(float v) {
    return __fdividef(2.0f, 1.0f + __expf(-2.0f * v)) - 1.0f;
}

// =====================================================================
// Kernel 1: x_gates[t][b][g] = x[b][t][:] @ W_ih[g][:] + b_ih[g]
// SMEM: w4 float4[16][3][128] (4 k-steps per float4), bias[384],
//       xT[64][36]. ~109KB -> 2 CTAs/SM.
// =====================================================================
#define XP_KB   (II / 4)         // 16 k-blocks
#define XP_HPAD 36
#define XP_SMEM_FLOATS (G3 * II + G3 + II * XP_HPAD)
#define NTILES (TT * (BATCH / 32))   // 15360

__global__ void __launch_bounds__(512)
xproj_kernel(const float* __restrict__ x,
             const float* __restrict__ Wih,
             const float* __restrict__ bih)
{
    extern __shared__ float sm[];
    float4* w4  = reinterpret_cast<float4*>(sm);   // [16][3][128] float4
    float* bias = sm + G3 * II;                    // [384]
    float* xT   = bias + G3;                       // [64][36]

    const int tid = threadIdx.x;

    // w4[(k0*3+g)*128 + jj] = Wih[n=g*128+jj][4k0..4k0+3]  (float4, contiguous)
    {
        const float4* W4g = reinterpret_cast<const float4*>(Wih);  // [384][16]
        for (int i = tid; i < G3 * XP_KB; i += 512) {
            int n  = i >> 4;        // 0..383
            int k0 = i & 15;        // 0..15
            int g  = n >> 7;
            int jj = n & 127;
            w4[(k0 * 3 + g) * 128 + jj] = W4g[i];
        }
    }
    for (int i = tid; i < G3; i += 512) bias[i] = bih[i];
    __syncthreads();

    const int j     = tid & 127;
    const int mg    = tid >> 7;
    const int mbase = mg * 8;
    const float br = bias[j], bz = bias[128 + j], bn = bias[256 + j];

    for (int tile = blockIdx.x; tile < NTILES; tile += gridDim.x) {
        const int t  = tile % TT;
        const int b0 = (tile / TT) << 5;

        // load x tile transposed: xT[k][m] = x[b0+m][t][k]
        for (int i = tid; i < 32 * II; i += 512) {
            int m = i >> 6;
            int k = i & 63;
            xT[k * XP_HPAD + m] = x[((size_t)(b0 + m) * TT + t) * II + k];
        }
        __syncthreads();

        u64 ar[4], az[4], an[4];
#pragma unroll
        for (int p = 0; p < 4; ++p) { ar[p] = 0ull; az[p] = 0ull; an[p] = 0ull; }

#pragma unroll 2
        for (int k0 = 0; k0 < XP_KB; ++k0) {
            const float4* wp = w4 + (k0 * 3) * 128 + j;
            float4 wr4 = wp[0];
            float4 wz4 = wp[128];
            float4 wn4 = wp[256];
#pragma unroll
            for (int kk = 0; kk < 4; ++kk) {
                float wr = (&wr4.x)[kk];
                float wz = (&wz4.x)[kk];
                float wn = (&wn4.x)[kk];
                u64 wr2 = pack2(wr, wr), wz2 = pack2(wz, wz), wn2 = pack2(wn, wn);
                const ulonglong2* hp = reinterpret_cast<const ulonglong2*>(
                    xT + (4 * k0 + kk) * XP_HPAD + mbase);
                ulonglong2 ha = hp[0];
                ulonglong2 hb = hp[1];
                u64 h2[4] = {ha.x, ha.y, hb.x, hb.y};
#pragma unroll
                for (int p = 0; p < 4; ++p) {
                    ar[p] = ffma2(h2[p], wr2, ar[p]);
                    az[p] = ffma2(h2[p], wz2, az[p]);
                    an[p] = ffma2(h2[p], wn2, an[p]);
                }
            }
        }

#pragma unroll
        for (int p = 0; p < 4; ++p) {
            float r0, r1, z0, z1, n0, n1;
            unpack2(ar[p], r0, r1);
            unpack2(az[p], z0, z1);
            unpack2(an[p], n0, n1);
#pragma unroll
            for (int e = 0; e < 2; ++e) {
                int mm = 2 * p + e;
                float vr = e ? r1 : r0;
                float vz = e ? z1 : z0;
                float vn = e ? n1 : n0;
                float* g = &g_xg[((size_t)t * BATCH + b0 + mbase + mm) * G3];
                g[j]       = vr + br;
                g[128 + j] = vz + bz;
                g[256 + j] = vn + bn;
            }
        }
        __syncthreads();
    }
}

// =====================================================================
// Kernel 2: fused GRU recurrence. 128 CTAs x 32 batch rows each.
// SMEM: w4 float4[32][3][128] (4 k per float4), bias[384], hT[128][36].
// Thread (j = tid&127, mg = tid>>7) owns gate columns {j, j+128, j+256}
// for rows mbase..mbase+7; h_old for those kept in registers.
// =====================================================================
#define R_KB   (HH / 4)          // 32 k-blocks
#define R_HPAD 36
#define R_SMEM_FLOATS (G3 * HH + G3 + HH * R_HPAD)

__global__ void __launch_bounds__(512)
gru_rec_kernel(const float* __restrict__ Whh,
               const float* __restrict__ bhh,
               float* __restrict__ out,
               int write_hT)
{
    extern __shared__ float sm[];
    float4* w4  = reinterpret_cast<float4*>(sm);   // [32][3][128] float4
    float* bias = sm + G3 * HH;                    // [384]
    float* hT   = bias + G3;                       // [128][36], hT[k][m]

    const int tid = threadIdx.x;

    // w4[(k0*3+g)*128 + jj] = Whh[n=g*128+jj][4k0..4k0+3]  (float4, contiguous)
    {
        const float4* W4g = reinterpret_cast<const float4*>(Whh);  // [384][32]
        for (int i = tid; i < G3 * R_KB; i += 512) {
            int n  = i >> 5;        // 0..383
            int k0 = i & 31;        // 0..31
            int g  = n >> 7;
            int jj = n & 127;
            w4[(k0 * 3 + g) * 128 + jj] = W4g[i];
        }
    }
    for (int i = tid; i < G3; i += 512) bias[i] = bhh[i];
    for (int i = tid; i < HH * R_HPAD; i += 512) hT[i] = 0.0f;
    __syncthreads();

    const int j     = tid & 127;
    const int mg    = tid >> 7;
    const int mbase = mg * 8;
    const int b0    = blockIdx.x << 5;
    const float br = bias[j], bz = bias[128 + j], bn = bias[256 + j];

    float hold[8];
#pragma unroll
    for (int mm = 0; mm < 8; ++mm) hold[mm] = 0.0f;

    for (int t = 0; t < TT; ++t) {
        // Prefetch input gates (independent of h; consumed in epilogue)
        float xr[8], xz[8], xn[8];
#pragma unroll
        for (int mm = 0; mm < 8; ++mm) {
            const float* g = &g_xg[((size_t)t * BATCH + b0 + mbase + mm) * G3];
            xr[mm] = g[j];
            xz[mm] = g[128 + j];
            xn[mm] = g[256 + j];
        }

        u64 ar[4], az[4], an[4];
#pragma unroll
        for (int p = 0; p < 4; ++p) { ar[p] = 0ull; az[p] = 0ull; an[p] = 0ull; }

#pragma unroll 2
        for (int k0 = 0; k0 < R_KB; ++k0) {
            const float4* wp = w4 + (k0 * 3) * 128 + j;
            float4 wr4 = wp[0];
            float4 wz4 = wp[128];
            float4 wn4 = wp[256];
#pragma unroll
            for (int kk = 0; kk < 4; ++kk) {
                float wr = (&wr4.x)[kk];
                float wz = (&wz4.x)[kk];
                float wn = (&wn4.x)[kk];
                u64 wr2 = pack2(wr, wr), wz2 = pack2(wz, wz), wn2 = pack2(wn, wn);
                const ulonglong2* hp = reinterpret_cast<const ulonglong2*>(
                    hT + (4 * k0 + kk) * R_HPAD + mbase);
                ulonglong2 ha = hp[0];   // broadcast (same addr across warp)
                ulonglong2 hb = hp[1];
                u64 h2[4] = {ha.x, ha.y, hb.x, hb.y};
#pragma unroll
                for (int p = 0; p < 4; ++p) {
                    ar[p] = ffma2(h2[p], wr2, ar[p]);
                    az[p] = ffma2(h2[p], wz2, az[p]);
                    an[p] = ffma2(h2[p], wn2, an[p]);
                }
            }
        }

        float hnew[8];
#pragma unroll
        for (int p = 0; p < 4; ++p) {
            float r0, r1, z0, z1, n0, n1;
            unpack2(ar[p], r0, r1);
            unpack2(az[p], z0, z1);
            unpack2(an[p], n0, n1);
#pragma unroll
            for (int e = 0; e < 2; ++e) {
                int mm = 2 * p + e;
                float hrv = e ? r1 : r0;
                float hzv = e ? z1 : z0;
                float hnv = e ? n1 : n0;
                float r  = sigf(xr[mm] + hrv + br);
                float z  = sigf(xz[mm] + hzv + bz);
                float nn = tanhf_fast(xn[mm] + r * (hnv + bn));
                float hv = nn + z * (hold[mm] - nn);
                hnew[mm] = hv;
                hold[mm] = hv;
                out[((size_t)(b0 + mbase + mm) * TT + t) * HH + j] = hv;
            }
        }
        __syncthreads();            // all reads of old h done
        {   // vectorized writeback: hT[j][mbase..mbase+7]
            float4* dst = reinterpret_cast<float4*>(hT + j * R_HPAD + mbase);
            dst[0] = make_float4(hnew[0], hnew[1], hnew[2], hnew[3]);
            dst[1] = make_float4(hnew[4], hnew[5], hnew[6], hnew[7]);
        }
        __syncthreads();            // new h visible before next step
    }

    if (write_hT) {
        float* outF = out + (size_t)BATCH * TT * HH;
#pragma unroll
        for (int mm = 0; mm < 8; ++mm)
            outF[(size_t)(b0 + mbase + mm) * HH + j] = hold[mm];
    }
}

// =====================================================================
extern "C" void kernel_launch(void* const* d_in, const int* in_sizes, int n_in,
                              void* d_out, int out_size)
{
    const float* x   = (const float*)d_in[0];
    const float* Wih = (const float*)d_in[1];
    const float* Whh = (const float*)d_in[2];
    const float* bih = (const float*)d_in[3];
    const float* bhh = (const float*)d_in[4];
    float* out = (float*)d_out;
    (void)in_sizes; (void)n_in;

    const int xp_smem = XP_SMEM_FLOATS * sizeof(float);   // ~109KB -> 2 CTA/SM
    const int r_smem  = R_SMEM_FLOATS  * sizeof(float);   // ~216.6 KB

    cudaFuncSetAttribute(xproj_kernel,
                         cudaFuncAttributeMaxDynamicSharedMemorySize, xp_smem);
    cudaFuncSetAttribute(gru_rec_kernel,
                         cudaFuncAttributeMaxDynamicSharedMemorySize, r_smem);

    int write_hT = (out_size >= BATCH * TT * HH + BATCH * HH) ? 1 : 0;

    xproj_kernel<<<296, 512, xp_smem>>>(x, Wih, bih);
    gru_rec_kernel<<<BATCH / 32, 512, r_smem>>>(Whh, bhh, out, write_hT);
}

// round 7
// speedup vs baseline: 1.6864x; 1.5398x over previous
#include <cuda_runtime.h>
#include <cuda_bf16.h>
#include <cstdint>

// Problem constants
#define BATCH 4096
#define TT    120
#define II    64
#define HH    128
#define G3    384   // 3*H

typedef unsigned long long u64;

// 755MB fp32 scratch for precomputed input gates, layout [T][B][3H]
__device__ float g_xg[(size_t)TT * BATCH * G3];

// ---------------- packed f32x2 helpers (sm_103a FFMA2) ----------------
__device__ __forceinline__ u64 ffma2(u64 a, u64 b, u64 c) {
    u64 d;
    asm("fma.rn.f32x2 %0, %1, %2, %3;" : "=l"(d) : "l"(a), "l"(b), "l"(c));
    return d;
}
__device__ __forceinline__ u64 pack2(float x, float y) {
    u64 d;
    asm("mov.b64 %0, {%1, %2};" : "=l"(d) : "f"(x), "f"(y));
    return d;
}
__device__ __forceinline__ void unpack2(u64 a, float& x, float& y) {
    asm("mov.b64 {%0, %1}, %2;" : "=f"(x), "=f"(y) : "l"(a));
}

__device__ __forceinline__ float sigf(float v) {
    return __fdividef(1.0f, 1.0f + __expf(-v));
}
__device__ __forceinline__ float tanhf_fast(float v) {
    return __fdividef(2.0f, 1.0f + __expf(-2.0f * v)) - 1.0f;
}

// ---------------- tensor-core helpers ----------------
__device__ __forceinline__ uint32_t s2u(const void* p) {
    return (uint32_t)__cvta_generic_to_shared(p);
}
__device__ __forceinline__ void ldsm_x4(uint32_t a[4], uint32_t addr) {
    asm volatile("ldmatrix.sync.aligned.m8n8.x4.shared.b16 {%0,%1,%2,%3}, [%4];"
                 : "=r"(a[0]), "=r"(a[1]), "=r"(a[2]), "=r"(a[3]) : "r"(addr));
}
// B operand: W stored [n][k] row-major == col-major B(k x n): load WITHOUT trans
__device__ __forceinline__ void ldsm_x2(uint32_t b[2], uint32_t addr) {
    asm volatile("ldmatrix.sync.aligned.m8n8.x2.shared.b16 {%0,%1}, [%2];"
                 : "=r"(b[0]), "=r"(b[1]) : "r"(addr));
}
__device__ __forceinline__ void mma16816(float c[4], const uint32_t a[4],
                                         const uint32_t b[2]) {
    asm volatile(
        "mma.sync.aligned.m16n8k16.row.col.f32.bf16.bf16.f32 "
        "{%0,%1,%2,%3}, {%4,%5,%6,%7}, {%8,%9}, {%0,%1,%2,%3};"
        : "+f"(c[0]), "+f"(c[1]), "+f"(c[2]), "+f"(c[3])
        : "r"(a[0]), "r"(a[1]), "r"(a[2]), "r"(a[3]), "r"(b[0]), "r"(b[1]));
}
// pack (lo_elem, hi_elem) -> bf16x2 (lo_elem in low halfword)
__device__ __forceinline__ uint32_t cvt_bf16x2(float lo_elem, float hi_elem) {
    uint32_t d;
    asm("cvt.rn.bf16x2.f32 %0, %1, %2;" : "=r"(d) : "f"(hi_elem), "f"(lo_elem));
    return d;
}

// =====================================================================
// Kernel 1: x_gates[t][b][g] = x[b][t][:] @ W_ih[g][:] + b_ih[g]
// (unchanged FFMA2 version)
// =====================================================================
#define XP_KB   (II / 4)
#define XP_HPAD 36
#define XP_SMEM_FLOATS (G3 * II + G3 + II * XP_HPAD)
#define NTILES (TT * (BATCH / 32))

__global__ void __launch_bounds__(512)
xproj_kernel(const float* __restrict__ x,
             const float* __restrict__ Wih,
             const float* __restrict__ bih)
{
    extern __shared__ float sm[];
    float4* w4  = reinterpret_cast<float4*>(sm);
    float* bias = sm + G3 * II;
    float* xT   = bias + G3;

    const int tid = threadIdx.x;

    {
        const float4* W4g = reinterpret_cast<const float4*>(Wih);
        for (int i = tid; i < G3 * XP_KB; i += 512) {
            int n  = i >> 4;
            int k0 = i & 15;
            int g  = n >> 7;
            int jj = n & 127;
            w4[(k0 * 3 + g) * 128 + jj] = W4g[i];
        }
    }
    for (int i = tid; i < G3; i += 512) bias[i] = bih[i];
    __syncthreads();

    const int j     = tid & 127;
    const int mg    = tid >> 7;
    const int mbase = mg * 8;
    const float br = bias[j], bz = bias[128 + j], bn = bias[256 + j];

    for (int tile = blockIdx.x; tile < NTILES; tile += gridDim.x) {
        const int t  = tile % TT;
        const int b0 = (tile / TT) << 5;

        for (int i = tid; i < 32 * II; i += 512) {
            int m = i >> 6;
            int k = i & 63;
            xT[k * XP_HPAD + m] = x[((size_t)(b0 + m) * TT + t) * II + k];
        }
        __syncthreads();

        u64 ar[4], az[4], an[4];
#pragma unroll
        for (int p = 0; p < 4; ++p) { ar[p] = 0ull; az[p] = 0ull; an[p] = 0ull; }

#pragma unroll 2
        for (int k0 = 0; k0 < XP_KB; ++k0) {
            const float4* wp = w4 + (k0 * 3) * 128 + j;
            float4 wr4 = wp[0];
            float4 wz4 = wp[128];
            float4 wn4 = wp[256];
#pragma unroll
            for (int kk = 0; kk < 4; ++kk) {
                float wr = (&wr4.x)[kk];
                float wz = (&wz4.x)[kk];
                float wn = (&wn4.x)[kk];
                u64 wr2 = pack2(wr, wr), wz2 = pack2(wz, wz), wn2 = pack2(wn, wn);
                const ulonglong2* hp = reinterpret_cast<const ulonglong2*>(
                    xT + (4 * k0 + kk) * XP_HPAD + mbase);
                ulonglong2 ha = hp[0];
                ulonglong2 hb = hp[1];
                u64 h2[4] = {ha.x, ha.y, hb.x, hb.y};
#pragma unroll
                for (int p = 0; p < 4; ++p) {
                    ar[p] = ffma2(h2[p], wr2, ar[p]);
                    az[p] = ffma2(h2[p], wz2, az[p]);
                    an[p] = ffma2(h2[p], wn2, an[p]);
                }
            }
        }

#pragma unroll
        for (int p = 0; p < 4; ++p) {
            float r0, r1, z0, z1, n0, n1;
            unpack2(ar[p], r0, r1);
            unpack2(az[p], z0, z1);
            unpack2(an[p], n0, n1);
#pragma unroll
            for (int e = 0; e < 2; ++e) {
                int mm = 2 * p + e;
                float vr = e ? r1 : r0;
                float vz = e ? z1 : z0;
                float vn = e ? n1 : n0;
                float* g = &g_xg[((size_t)t * BATCH + b0 + mbase + mm) * G3];
                g[j]       = vr + br;
                g[128 + j] = vz + bz;
                g[256 + j] = vn + bn;
            }
        }
        __syncthreads();
    }
}

// =====================================================================
// Kernel 2: GRU recurrence on tensor cores (mma.sync bf16 hi/lo split).
// 128 CTAs x 32 batch rows. Per step: C[32x384] = h[32x128] @ Whh^T.
// Warp w owns n-tiles {w, w+16, w+32} -> j columns 8w..8w+7 for all 3
// gates; gate math entirely in registers on matching C-frag lanes.
// SMEM: Whi/Wlo [384][136] bf16, Hhi/Hlo [32][136] bf16. 226.3 KB.
// =====================================================================
#define WPAD  136          // bf16 per row (272 B stride)
#define R_SMEM_BYTES ((384 * WPAD * 2 + 32 * WPAD * 2) * 2)   // 226304

__global__ void __launch_bounds__(512, 1)
gru_mma_kernel(const float* __restrict__ Whh,
               const float* __restrict__ bhh,
               float* __restrict__ out,
               int write_hT)
{
    extern __shared__ __align__(16) char smemc[];
    __nv_bfloat16* Whi = reinterpret_cast<__nv_bfloat16*>(smemc);
    __nv_bfloat16* Wlo = Whi + 384 * WPAD;
    __nv_bfloat16* Hhi = Wlo + 384 * WPAD;
    __nv_bfloat16* Hlo = Hhi + 32 * WPAD;

    const int tid   = threadIdx.x;
    const int w     = tid >> 5;          // 0..15
    const int lane  = tid & 31;
    const int g8    = lane >> 2;         // 0..7  (groupID)
    const int cc    = lane & 3;          // 0..3
    const int jbase = w * 8;
    const int j0    = jbase + 2 * cc;    // this thread's first j column
    const int b0    = blockIdx.x * 32;

    // ---- fill W hi/lo planes (fp32 -> bf16 + residual) ----
    for (int i = tid; i < G3 * HH; i += 512) {
        int n = i >> 7, k = i & 127;
        float v = Whh[i];
        __nv_bfloat16 hi = __float2bfloat16(v);
        float lo = v - __bfloat162float(hi);
        Whi[n * WPAD + k] = hi;
        Wlo[n * WPAD + k] = __float2bfloat16(lo);
    }
    // ---- zero h planes ----
    for (int i = tid; i < 32 * WPAD; i += 512) {
        Hhi[i] = __float2bfloat16(0.0f);
        Hlo[i] = __float2bfloat16(0.0f);
    }

    // bias registers for this thread's 6 (gate, col) slots
    const float bR0 = bhh[j0],       bR1 = bhh[j0 + 1];
    const float bZ0 = bhh[128 + j0], bZ1 = bhh[128 + j0 + 1];
    const float bN0 = bhh[256 + j0], bN1 = bhh[256 + j0 + 1];

    __syncthreads();

    // ---- ldmatrix base addresses ----
    // A (h): x4, lanes 0-15 rows, lanes 16-31 same rows at +8 k-cols
    const int arow = lane & 15;
    const int acol = (lane >> 4) * 8;
    uint32_t aHi[2], aLo[2];
#pragma unroll
    for (int mt = 0; mt < 2; ++mt) {
        aHi[mt] = s2u(Hhi + (mt * 16 + arow) * WPAD + acol);
        aLo[mt] = s2u(Hlo + (mt * 16 + arow) * WPAD + acol);
    }
    // B (W): x2 non-trans. lanes 0-7 -> W rows nb+0..7 (k 0-7),
    // lanes 8-15 -> same rows at k 8-15.
    const int l16  = lane & 15;
    const int brow = l16 & 7;
    const int bkh  = (l16 >> 3) & 1;
    uint32_t bHi[3], bLo[3];
#pragma unroll
    for (int g = 0; g < 3; ++g) {
        int nb = g * 128 + jbase;
        bHi[g] = s2u(Whi + (nb + brow) * WPAD + 8 * bkh);
        bLo[g] = s2u(Wlo + (nb + brow) * WPAD + 8 * bkh);
    }

    // hold: 4 row-instances (q = mt*2+rp) x 2 cols
    float hold[4][2];
#pragma unroll
    for (int q = 0; q < 4; ++q) { hold[q][0] = 0.0f; hold[q][1] = 0.0f; }

    for (int t = 0; t < TT; ++t) {
        // ---- prefetch input gates (DRAM, hidden under the mma loop) ----
        float2 xr[4], xz[4], xn[4];
        const float* gp = g_xg + ((size_t)t * BATCH + b0) * G3;
#pragma unroll
        for (int q = 0; q < 4; ++q) {
            int bl = (q >> 1) * 16 + g8 + (q & 1) * 8;
            const float* row = gp + (size_t)bl * G3 + j0;
            xr[q] = *reinterpret_cast<const float2*>(row);
            xz[q] = *reinterpret_cast<const float2*>(row + 128);
            xn[q] = *reinterpret_cast<const float2*>(row + 256);
        }

        // ---- tensor-core GEMM: C[mt][gate][4] ----
        float C[2][3][4];
#pragma unroll
        for (int mt = 0; mt < 2; ++mt)
#pragma unroll
            for (int g = 0; g < 3; ++g)
#pragma unroll
                for (int e = 0; e < 4; ++e) C[mt][g][e] = 0.0f;

#pragma unroll
        for (int c8 = 0; c8 < 8; ++c8) {
            const uint32_t off = c8 * 32;   // 16 bf16 = 32 bytes per k-chunk
            uint32_t ahi[2][4], alo[2][4];
            ldsm_x4(ahi[0], aHi[0] + off);
            ldsm_x4(ahi[1], aHi[1] + off);
            ldsm_x4(alo[0], aLo[0] + off);
            ldsm_x4(alo[1], aLo[1] + off);
#pragma unroll
            for (int g = 0; g < 3; ++g) {
                uint32_t bh[2], bl_[2];
                ldsm_x2(bh,  bHi[g] + off);
                ldsm_x2(bl_, bLo[g] + off);
#pragma unroll
                for (int mt = 0; mt < 2; ++mt) {
                    mma16816(C[mt][g], ahi[mt], bh);
                    mma16816(C[mt][g], alo[mt], bh);
                    mma16816(C[mt][g], ahi[mt], bl_);
                }
            }
        }
        __syncthreads();   // all ldmatrix reads of h done before rewrite

        // ---- gates + h update + stores ----
#pragma unroll
        for (int mt = 0; mt < 2; ++mt) {
#pragma unroll
            for (int rp = 0; rp < 2; ++rp) {
                const int q   = mt * 2 + rp;
                const int row = mt * 16 + g8 + rp * 8;   // local batch row
                float hr0 = C[mt][0][rp * 2],  hr1 = C[mt][0][rp * 2 + 1];
                float hz0 = C[mt][1][rp * 2],  hz1 = C[mt][1][rp * 2 + 1];
                float hn0 = C[mt][2][rp * 2],  hn1 = C[mt][2][rp * 2 + 1];

                float r0 = sigf(xr[q].x + hr0 + bR0);
                float r1 = sigf(xr[q].y + hr1 + bR1);
                float z0 = sigf(xz[q].x + hz0 + bZ0);
                float z1 = sigf(xz[q].y + hz1 + bZ1);
                float n0 = tanhf_fast(xn[q].x + r0 * (hn0 + bN0));
                float n1 = tanhf_fast(xn[q].y + r1 * (hn1 + bN1));
                float h0 = n0 + z0 * (hold[q][0] - n0);
                float h1 = n1 + z1 * (hold[q][1] - n1);
                hold[q][0] = h0; hold[q][1] = h1;

                // split h -> bf16 hi/lo planes
                __nv_bfloat16 h0h = __float2bfloat16(h0);
                __nv_bfloat16 h1h = __float2bfloat16(h1);
                float l0 = h0 - __bfloat162float(h0h);
                float l1 = h1 - __bfloat162float(h1h);
                uint32_t phi, plo;
                asm("mov.b32 %0, {%1, %2};" : "=r"(phi)
                    : "h"(*(const unsigned short*)&h0h),
                      "h"(*(const unsigned short*)&h1h));
                plo = cvt_bf16x2(l0, l1);
                *reinterpret_cast<uint32_t*>(&Hhi[row * WPAD + j0]) = phi;
                *reinterpret_cast<uint32_t*>(&Hlo[row * WPAD + j0]) = plo;

                // output
                float2 o; o.x = h0; o.y = h1;
                *reinterpret_cast<float2*>(
                    &out[((size_t)(b0 + row) * TT + t) * HH + j0]) = o;
            }
        }
        __syncthreads();   // new h visible before next step's ldmatrix
    }

    if (write_hT) {
        float* outF = out + (size_t)BATCH * TT * HH;
#pragma unroll
        for (int q = 0; q < 4; ++q) {
            int row = (q >> 1) * 16 + g8 + (q & 1) * 8;
            float2 o; o.x = hold[q][0]; o.y = hold[q][1];
            *reinterpret_cast<float2*>(&outF[(size_t)(b0 + row) * HH + j0]) = o;
        }
    }
}

// =====================================================================
extern "C" void kernel_launch(void* const* d_in, const int* in_sizes, int n_in,
                              void* d_out, int out_size)
{
    const float* x   = (const float*)d_in[0];
    const float* Wih = (const float*)d_in[1];
    const float* Whh = (const float*)d_in[2];
    const float* bih = (const float*)d_in[3];
    const float* bhh = (const float*)d_in[4];
    float* out = (float*)d_out;
    (void)in_sizes; (void)n_in;

    const int xp_smem = XP_SMEM_FLOATS * sizeof(float);   // ~109KB -> 2 CTA/SM

    cudaFuncSetAttribute(xproj_kernel,
                         cudaFuncAttributeMaxDynamicSharedMemorySize, xp_smem);
    cudaFuncSetAttribute(gru_mma_kernel,
                         cudaFuncAttributeMaxDynamicSharedMemorySize, R_SMEM_BYTES);

    int write_hT = (out_size >= BATCH * TT * HH + BATCH * HH) ? 1 : 0;

    xproj_kernel<<<296, 512, xp_smem>>>(x, Wih, bih);
    gru_mma_kernel<<<BATCH / 32, 512, R_SMEM_BYTES>>>(Whh, bhh, out, write_hT);
}

// round 9
// speedup vs baseline: 2.4787x; 1.4698x over previous
#include <cuda_runtime.h>
#include <cuda_bf16.h>
#include <cstdint>

// Problem constants
#define BATCH 4096
#define TT    120
#define II    64
#define HH    128
#define G3    384   // 3*H

// 755MB fp32 scratch for precomputed input gates, layout [T][B][3H]
__device__ float g_xg[(size_t)TT * BATCH * G3];

__device__ __forceinline__ float sigf(float v) {
    return __fdividef(1.0f, 1.0f + __expf(-v));
}
__device__ __forceinline__ float tanhf_fast(float v) {
    return __fdividef(2.0f, 1.0f + __expf(-2.0f * v)) - 1.0f;
}

// ---------------- tensor-core helpers ----------------
__device__ __forceinline__ uint32_t s2u(const void* p) {
    return (uint32_t)__cvta_generic_to_shared(p);
}
__device__ __forceinline__ void ldsm_x4(uint32_t a[4], uint32_t addr) {
    asm volatile("ldmatrix.sync.aligned.m8n8.x4.shared.b16 {%0,%1,%2,%3}, [%4];"
                 : "=r"(a[0]), "=r"(a[1]), "=r"(a[2]), "=r"(a[3]) : "r"(addr));
}
// B operand: W stored [n][k] row-major == col-major B(k x n): load WITHOUT trans
__device__ __forceinline__ void ldsm_x2(uint32_t b[2], uint32_t addr) {
    asm volatile("ldmatrix.sync.aligned.m8n8.x2.shared.b16 {%0,%1}, [%2];"
                 : "=r"(b[0]), "=r"(b[1]) : "r"(addr));
}
__device__ __forceinline__ void mma16816(float c[4], const uint32_t a[4],
                                         const uint32_t b[2]) {
    asm volatile(
        "mma.sync.aligned.m16n8k16.row.col.f32.bf16.bf16.f32 "
        "{%0,%1,%2,%3}, {%4,%5,%6,%7}, {%8,%9}, {%0,%1,%2,%3};"
        : "+f"(c[0]), "+f"(c[1]), "+f"(c[2]), "+f"(c[3])
        : "r"(a[0]), "r"(a[1]), "r"(a[2]), "r"(a[3]), "r"(b[0]), "r"(b[1]));
}
// pack (lo_elem, hi_elem) floats -> bf16x2 with rounding (lo_elem in low half)
__device__ __forceinline__ uint32_t cvt_bf16x2(float lo_elem, float hi_elem) {
    uint32_t d;
    asm("cvt.rn.bf16x2.f32 %0, %1, %2;" : "=r"(d) : "f"(hi_elem), "f"(lo_elem));
    return d;
}
// pack two already-converted bf16 (a -> low half)
__device__ __forceinline__ uint32_t pack_bf16x2(__nv_bfloat16 a, __nv_bfloat16 b) {
    uint32_t d;
    asm("mov.b32 %0, {%1, %2};" : "=r"(d)
        : "h"(*(const unsigned short*)&a), "h"(*(const unsigned short*)&b));
    return d;
}

// =====================================================================
// Kernel 1: x_gates via tensor cores (bf16 hi/lo 3-pass mma).
// Persistent 148 CTAs x 512 thr. Tile = 64 batch rows x 1 timestep.
// SMEM: Wih hi/lo [384][72] bf16, X hi/lo [64][72] bf16 (~126 KB).
// Warp w owns n-cols 8w..8w+7 for all 3 gates (n-tiles {w,w+16,w+32}).
// Next tile's x prefetched into registers under the current tile's mma.
// =====================================================================
#define XW   72                  // padded k-row length (144B stride)
#define NT2  (TT * (BATCH / 64)) // 7680 tiles
#define XP2_SMEM_BYTES ((G3 * XW * 2 + 64 * XW * 2) * 2)   // 129024

__global__ void __launch_bounds__(512, 1)
xproj_mma_kernel(const float* __restrict__ x,
                 const float* __restrict__ Wih,
                 const float* __restrict__ bih)
{
    extern __shared__ __align__(16) char smemc[];
    __nv_bfloat16* Whi = reinterpret_cast<__nv_bfloat16*>(smemc);
    __nv_bfloat16* Wlo = Whi + G3 * XW;
    __nv_bfloat16* Xhi = Wlo + G3 * XW;
    __nv_bfloat16* Xlo = Xhi + 64 * XW;

    const int tid   = threadIdx.x;
    const int w     = tid >> 5;
    const int lane  = tid & 31;
    const int g8    = lane >> 2;
    const int cc    = lane & 3;
    const int jbase = w * 8;
    const int j0    = jbase + 2 * cc;

    // ---- Wih -> hi/lo planes ----
    for (int i = tid; i < G3 * II; i += 512) {
        int n = i >> 6, k = i & 63;
        float v = Wih[i];
        __nv_bfloat16 hi = __float2bfloat16(v);
        Whi[n * XW + k] = hi;
        Wlo[n * XW + k] = __float2bfloat16(v - __bfloat162float(hi));
    }

    const float bR0 = bih[j0],       bR1 = bih[j0 + 1];
    const float bZ0 = bih[128 + j0], bZ1 = bih[128 + j0 + 1];
    const float bN0 = bih[256 + j0], bN1 = bih[256 + j0 + 1];

    // ---- ldmatrix addresses ----
    const int arow = lane & 15;
    const int acol = (lane >> 4) * 8;
    uint32_t aHi[4], aLo[4];
#pragma unroll
    for (int mt = 0; mt < 4; ++mt) {
        aHi[mt] = s2u(Xhi + (mt * 16 + arow) * XW + acol);
        aLo[mt] = s2u(Xlo + (mt * 16 + arow) * XW + acol);
    }
    const int l16  = lane & 15;
    const int brow = l16 & 7;
    const int bkh  = (l16 >> 3) & 1;
    uint32_t bHi[3], bLo[3];
#pragma unroll
    for (int g = 0; g < 3; ++g) {
        int nb = g * 128 + jbase;
        bHi[g] = s2u(Whi + (nb + brow) * XW + 8 * bkh);
        bLo[g] = s2u(Wlo + (nb + brow) * XW + 8 * bkh);
    }

    // x prefetch slots: thread covers row tid>>3, cols (tid&7)*8 .. +7
    const int xrow = tid >> 3;
    const int xcol = (tid & 7) * 8;
    float4 pa, pb;

    int tile = blockIdx.x;
    if (tile < NT2) {
        int t = tile % TT, b0 = (tile / TT) << 6;
        const float4* p = reinterpret_cast<const float4*>(
            x + ((size_t)(b0 + xrow) * TT + t) * II + xcol);
        pa = p[0]; pb = p[1];
    }

    for (; tile < NT2; tile += 148) {
        const int t  = tile % TT;
        const int b0 = (tile / TT) << 6;

        __syncthreads();   // prior tile's ldmatrix reads complete

        // store prefetched x into hi/lo planes
        {
            float v[8] = {pa.x, pa.y, pa.z, pa.w, pb.x, pb.y, pb.z, pb.w};
            __nv_bfloat16* hp = Xhi + xrow * XW + xcol;
            __nv_bfloat16* lp = Xlo + xrow * XW + xcol;
#pragma unroll
            for (int e = 0; e < 4; ++e) {
                float a0 = v[2 * e], a1 = v[2 * e + 1];
                __nv_bfloat16 h0 = __float2bfloat16(a0);
                __nv_bfloat16 h1 = __float2bfloat16(a1);
                *reinterpret_cast<uint32_t*>(hp + 2 * e) = pack_bf16x2(h0, h1);
                *reinterpret_cast<uint32_t*>(lp + 2 * e) =
                    cvt_bf16x2(a0 - __bfloat162float(h0), a1 - __bfloat162float(h1));
            }
        }

        // prefetch next tile
        {
            int nxt = tile + 148;
            if (nxt < NT2) {
                int tn = nxt % TT, bn = (nxt / TT) << 6;
                const float4* p = reinterpret_cast<const float4*>(
                    x + ((size_t)(bn + xrow) * TT + tn) * II + xcol);
                pa = p[0]; pb = p[1];
            }
        }

        __syncthreads();   // planes visible

        float C[4][3][4];
#pragma unroll
        for (int mt = 0; mt < 4; ++mt)
#pragma unroll
            for (int g = 0; g < 3; ++g)
#pragma unroll
                for (int e = 0; e < 4; ++e) C[mt][g][e] = 0.0f;

#pragma unroll
        for (int c8 = 0; c8 < 4; ++c8) {
            const uint32_t off = c8 * 32;   // 16 bf16 = 32 B
            uint32_t ahi[4][4], alo[4][4];
#pragma unroll
            for (int mt = 0; mt < 4; ++mt) {
                ldsm_x4(ahi[mt], aHi[mt] + off);
                ldsm_x4(alo[mt], aLo[mt] + off);
            }
#pragma unroll
            for (int g = 0; g < 3; ++g) {
                uint32_t bh[2], bl_[2];
                ldsm_x2(bh,  bHi[g] + off);
                ldsm_x2(bl_, bLo[g] + off);
#pragma unroll
                for (int mt = 0; mt < 4; ++mt) {
                    mma16816(C[mt][g], ahi[mt], bh);
                    mma16816(C[mt][g], alo[mt], bh);
                    mma16816(C[mt][g], ahi[mt], bl_);
                }
            }
        }

        // epilogue: add bias, store fp32 to g_xg[t][b][gate*128+j]
#pragma unroll
        for (int mt = 0; mt < 4; ++mt) {
#pragma unroll
            for (int rp = 0; rp < 2; ++rp) {
                int row = mt * 16 + g8 + rp * 8;
                float* dst = g_xg + ((size_t)t * BATCH + b0 + row) * G3 + j0;
                float2 o;
                o.x = C[mt][0][rp * 2] + bR0; o.y = C[mt][0][rp * 2 + 1] + bR1;
                *reinterpret_cast<float2*>(dst) = o;
                o.x = C[mt][1][rp * 2] + bZ0; o.y = C[mt][1][rp * 2 + 1] + bZ1;
                *reinterpret_cast<float2*>(dst + 128) = o;
                o.x = C[mt][2][rp * 2] + bN0; o.y = C[mt][2][rp * 2 + 1] + bN1;
                *reinterpret_cast<float2*>(dst + 256) = o;
            }
        }
    }
}

// =====================================================================
// Kernel 2: GRU recurrence on tensor cores (unchanged from R7 pass).
// =====================================================================
#define WPAD  136
#define R_SMEM_BYTES ((384 * WPAD * 2 + 32 * WPAD * 2) * 2)   // 226304

__global__ void __launch_bounds__(512, 1)
gru_mma_kernel(const float* __restrict__ Whh,
               const float* __restrict__ bhh,
               float* __restrict__ out,
               int write_hT)
{
    extern __shared__ __align__(16) char smemc[];
    __nv_bfloat16* Whi = reinterpret_cast<__nv_bfloat16*>(smemc);
    __nv_bfloat16* Wlo = Whi + 384 * WPAD;
    __nv_bfloat16* Hhi = Wlo + 384 * WPAD;
    __nv_bfloat16* Hlo = Hhi + 32 * WPAD;

    const int tid   = threadIdx.x;
    const int w     = tid >> 5;
    const int lane  = tid & 31;
    const int g8    = lane >> 2;
    const int cc    = lane & 3;
    const int jbase = w * 8;
    const int j0    = jbase + 2 * cc;
    const int b0    = blockIdx.x * 32;

    for (int i = tid; i < G3 * HH; i += 512) {
        int n = i >> 7, k = i & 127;
        float v = Whh[i];
        __nv_bfloat16 hi = __float2bfloat16(v);
        float lo = v - __bfloat162float(hi);
        Whi[n * WPAD + k] = hi;
        Wlo[n * WPAD + k] = __float2bfloat16(lo);
    }
    for (int i = tid; i < 32 * WPAD; i += 512) {
        Hhi[i] = __float2bfloat16(0.0f);
        Hlo[i] = __float2bfloat16(0.0f);
    }

    const float bR0 = bhh[j0],       bR1 = bhh[j0 + 1];
    const float bZ0 = bhh[128 + j0], bZ1 = bhh[128 + j0 + 1];
    const float bN0 = bhh[256 + j0], bN1 = bhh[256 + j0 + 1];

    __syncthreads();

    const int arow = lane & 15;
    const int acol = (lane >> 4) * 8;
    uint32_t aHi[2], aLo[2];
#pragma unroll
    for (int mt = 0; mt < 2; ++mt) {
        aHi[mt] = s2u(Hhi + (mt * 16 + arow) * WPAD + acol);
        aLo[mt] = s2u(Hlo + (mt * 16 + arow) * WPAD + acol);
    }
    const int l16  = lane & 15;
    const int brow = l16 & 7;
    const int bkh  = (l16 >> 3) & 1;
    uint32_t bHi[3], bLo[3];
#pragma unroll
    for (int g = 0; g < 3; ++g) {
        int nb = g * 128 + jbase;
        bHi[g] = s2u(Whi + (nb + brow) * WPAD + 8 * bkh);
        bLo[g] = s2u(Wlo + (nb + brow) * WPAD + 8 * bkh);
    }

    float hold[4][2];
#pragma unroll
    for (int q = 0; q < 4; ++q) { hold[q][0] = 0.0f; hold[q][1] = 0.0f; }

    for (int t = 0; t < TT; ++t) {
        float2 xr[4], xz[4], xn[4];
        const float* gp = g_xg + ((size_t)t * BATCH + b0) * G3;
#pragma unroll
        for (int q = 0; q < 4; ++q) {
            int bl = (q >> 1) * 16 + g8 + (q & 1) * 8;
            const float* row = gp + (size_t)bl * G3 + j0;
            xr[q] = *reinterpret_cast<const float2*>(row);
            xz[q] = *reinterpret_cast<const float2*>(row + 128);
            xn[q] = *reinterpret_cast<const float2*>(row + 256);
        }

        float C[2][3][4];
#pragma unroll
        for (int mt = 0; mt < 2; ++mt)
#pragma unroll
            for (int g = 0; g < 3; ++g)
#pragma unroll
                for (int e = 0; e < 4; ++e) C[mt][g][e] = 0.0f;

#pragma unroll
        for (int c8 = 0; c8 < 8; ++c8) {
            const uint32_t off = c8 * 32;
            uint32_t ahi[2][4], alo[2][4];
            ldsm_x4(ahi[0], aHi[0] + off);
            ldsm_x4(ahi[1], aHi[1] + off);
            ldsm_x4(alo[0], aLo[0] + off);
            ldsm_x4(alo[1], aLo[1] + off);
#pragma unroll
            for (int g = 0; g < 3; ++g) {
                uint32_t bh[2], bl_[2];
                ldsm_x2(bh,  bHi[g] + off);
                ldsm_x2(bl_, bLo[g] + off);
#pragma unroll
                for (int mt = 0; mt < 2; ++mt) {
                    mma16816(C[mt][g], ahi[mt], bh);
                    mma16816(C[mt][g], alo[mt], bh);
                    mma16816(C[mt][g], ahi[mt], bl_);
                }
            }
        }
        __syncthreads();

#pragma unroll
        for (int mt = 0; mt < 2; ++mt) {
#pragma unroll
            for (int rp = 0; rp < 2; ++rp) {
                const int q   = mt * 2 + rp;
                const int row = mt * 16 + g8 + rp * 8;
                float hr0 = C[mt][0][rp * 2],  hr1 = C[mt][0][rp * 2 + 1];
                float hz0 = C[mt][1][rp * 2],  hz1 = C[mt][1][rp * 2 + 1];
                float hn0 = C[mt][2][rp * 2],  hn1 = C[mt][2][rp * 2 + 1];

                float r0 = sigf(xr[q].x + hr0 + bR0);
                float r1 = sigf(xr[q].y + hr1 + bR1);
                float z0 = sigf(xz[q].x + hz0 + bZ0);
                float z1 = sigf(xz[q].y + hz1 + bZ1);
                float n0 = tanhf_fast(xn[q].x + r0 * (hn0 + bN0));
                float n1 = tanhf_fast(xn[q].y + r1 * (hn1 + bN1));
                float h0 = n0 + z0 * (hold[q][0] - n0);
                float h1 = n1 + z1 * (hold[q][1] - n1);
                hold[q][0] = h0; hold[q][1] = h1;

                __nv_bfloat16 h0h = __float2bfloat16(h0);
                __nv_bfloat16 h1h = __float2bfloat16(h1);
                float l0 = h0 - __bfloat162float(h0h);
                float l1 = h1 - __bfloat162float(h1h);
                *reinterpret_cast<uint32_t*>(&Hhi[row * WPAD + j0]) =
                    pack_bf16x2(h0h, h1h);
                *reinterpret_cast<uint32_t*>(&Hlo[row * WPAD + j0]) =
                    cvt_bf16x2(l0, l1);

                float2 o; o.x = h0; o.y = h1;
                *reinterpret_cast<float2*>(
                    &out[((size_t)(b0 + row) * TT + t) * HH + j0]) = o;
            }
        }
        __syncthreads();
    }

    if (write_hT) {
        float* outF = out + (size_t)BATCH * TT * HH;
#pragma unroll
        for (int q = 0; q < 4; ++q) {
            int row = (q >> 1) * 16 + g8 + (q & 1) * 8;
            float2 o; o.x = hold[q][0]; o.y = hold[q][1];
            *reinterpret_cast<float2*>(&outF[(size_t)(b0 + row) * HH + j0]) = o;
        }
    }
}

// =====================================================================
extern "C" void kernel_launch(void* const* d_in, const int* in_sizes, int n_in,
                              void* d_out, int out_size)
{
    const float* x   = (const float*)d_in[0];
    const float* Wih = (const float*)d_in[1];
    const float* Whh = (const float*)d_in[2];
    const float* bih = (const float*)d_in[3];
    const float* bhh = (const float*)d_in[4];
    float* out = (float*)d_out;
    (void)in_sizes; (void)n_in;

    cudaFuncSetAttribute(xproj_mma_kernel,
                         cudaFuncAttributeMaxDynamicSharedMemorySize, XP2_SMEM_BYTES);
    cudaFuncSetAttribute(gru_mma_kernel,
                         cudaFuncAttributeMaxDynamicSharedMemorySize, R_SMEM_BYTES);

    int write_hT = (out_size >= BATCH * TT * HH + BATCH * HH) ? 1 : 0;

    xproj_mma_kernel<<<148, 512, XP2_SMEM_BYTES>>>(x, Wih, bih);
    gru_mma_kernel<<<BATCH / 32, 512, R_SMEM_BYTES>>>(Whh, bhh, out, write_hT);
}